// round 8
// baseline (speedup 1.0000x reference)
#include <cuda_runtime.h>
#include <cuda_bf16.h>

// Q_Model_43782896615432 — analytic collapse of the 6-qubit circuit.
//   Z0=c1*c2, Z1=c0*c1, Z2=c0*c1*c2, Z3=c4*c5, Z4=c3*c4, Z5=c3*c4*c5
// R8: R5's winning shape (2 samples/thread, 4096 warps, vec I/O, smem
// weights) but with single-warp blocks (TPB=32): the 2-warp BAR.SYNC whose
// release was gated on the weight-load DRAM/L2 trip becomes a ~23-cycle
// __syncwarp, and 4096 blocks give finer wave packing (3.6% tail vs 7%).

#define BQ 262144
#define TPB 32

__global__ __launch_bounds__(TPB)
void q_model_kernel(const float* __restrict__ sa,
                    const float* __restrict__ sen,
                    const float* __restrict__ W_sar,  const float* __restrict__ b_sar,
                    const float* __restrict__ W_sen,  const float* __restrict__ b_sen,
                    const float* __restrict__ W_resar, const float* __restrict__ b_resar,
                    const float* __restrict__ W_resen, const float* __restrict__ b_resen,
                    float* __restrict__ out)
{
    const int t = threadIdx.x;                   // 0..31, one warp per block
    const int g = blockIdx.x * TPB + t;          // 0 .. 131071, exact (2 samples each)

    // ---- issue all 6 input LDG.64 FIRST (MLP=6, overlaps weight staging) ----
    const float2* sen2 = reinterpret_cast<const float2*>(sen) + 3 * g;
    const float2* sa2  = reinterpret_cast<const float2*>(sa)  + 3 * g;
    const float2 E0 = sen2[0];
    const float2 E1 = sen2[1];
    const float2 E2 = sen2[2];
    const float2 A0 = sa2[0];
    const float2 A1 = sa2[1];
    const float2 A2 = sa2[2];

    // ---- stage 44 params into smem: rows of (w0, w1, w2, bias) ----
    // rows 0-2: W_sen/b_sen | 3-5: W_sar/b_sar | 6-7: W_resar/b_resar | 8-10: W_resen/b_resen
    __shared__ float4 P[11];
#pragma unroll
    for (int k = t; k < 44; k += TPB) {
        const int row = k >> 2;
        const int c   = k & 3;
        float v;
        if (row < 3)      v = (c < 3) ? W_sen[row * 3 + c]         : b_sen[row];
        else if (row < 6) v = (c < 3) ? W_sar[(row - 3) * 3 + c]   : b_sar[row - 3];
        else if (row < 8) v = (c < 3) ? W_resar[(row - 6) * 3 + c] : b_resar[row - 6];
        else              v = (c < 3) ? W_resen[(row - 8) * 3 + c] : b_resen[row - 8];
        reinterpret_cast<float*>(P)[k] = v;
    }
    __syncwarp();   // single warp: no BAR.SYNC needed

    // ---- param rows (broadcast LDS.128, register-resident) ----
    const float4 r0 = P[0], r1 = P[1], r2 = P[2];   // theta 0-2 (sen branch)
    const float4 r3 = P[3], r4 = P[4], r5 = P[5];   // theta 3-5 (sa branch)
    const float4 q0 = P[6], q1 = P[7];              // sar output rows
    const float4 u0 = P[8], u1 = P[9], u2 = P[10];  // sen output rows

    const float ein[6] = {E0.x, E0.y, E1.x, E1.y, E2.x, E2.y};
    const float ain[6] = {A0.x, A0.y, A1.x, A1.y, A2.x, A2.y};

    float sarv[4];
    float senv[6];

#pragma unroll
    for (int s = 0; s < 2; s++) {
        const float e0 = ein[3 * s + 0], e1 = ein[3 * s + 1], e2 = ein[3 * s + 2];
        const float a0 = ain[3 * s + 0], a1 = ain[3 * s + 1], a2 = ain[3 * s + 2];

        const float t0 = fmaf(r0.x, e0, fmaf(r0.y, e1, fmaf(r0.z, e2, r0.w)));
        const float t1 = fmaf(r1.x, e0, fmaf(r1.y, e1, fmaf(r1.z, e2, r1.w)));
        const float t2 = fmaf(r2.x, e0, fmaf(r2.y, e1, fmaf(r2.z, e2, r2.w)));
        const float t3 = fmaf(r3.x, a0, fmaf(r3.y, a1, fmaf(r3.z, a2, r3.w)));
        const float t4 = fmaf(r4.x, a0, fmaf(r4.y, a1, fmaf(r4.z, a2, r4.w)));
        const float t5 = fmaf(r5.x, a0, fmaf(r5.y, a1, fmaf(r5.z, a2, r5.w)));

        const float c0 = __cosf(t0), c1 = __cosf(t1), c2 = __cosf(t2);
        const float c3 = __cosf(t3), c4 = __cosf(t4), c5 = __cosf(t5);

        const float Z0 = c1 * c2;
        const float Z1 = c0 * c1;
        const float Z2 = Z1 * c2;
        const float Z3 = c4 * c5;
        const float Z4 = c3 * c4;
        const float Z5 = Z4 * c5;

        sarv[2 * s + 0] = fmaf(q0.x, Z3, fmaf(q0.y, Z4, fmaf(q0.z, Z5, q0.w)));
        sarv[2 * s + 1] = fmaf(q1.x, Z3, fmaf(q1.y, Z4, fmaf(q1.z, Z5, q1.w)));

        senv[3 * s + 0] = fmaf(u0.x, Z0, fmaf(u0.y, Z1, fmaf(u0.z, Z2, u0.w)));
        senv[3 * s + 1] = fmaf(u1.x, Z0, fmaf(u1.y, Z1, fmaf(u1.z, Z2, u1.w)));
        senv[3 * s + 2] = fmaf(u2.x, Z0, fmaf(u2.y, Z1, fmaf(u2.z, Z2, u2.w)));
    }

    // ---- outputs: sar [0, 2B) as STG.128; sen [2B, 5B) as 3x STG.64 ----
    reinterpret_cast<float4*>(out)[g] = make_float4(sarv[0], sarv[1], sarv[2], sarv[3]);

    float2* so = reinterpret_cast<float2*>(out + 2 * BQ) + 3 * g;
    so[0] = make_float2(senv[0], senv[1]);
    so[1] = make_float2(senv[2], senv[3]);
    so[2] = make_float2(senv[4], senv[5]);
}

extern "C" void kernel_launch(void* const* d_in, const int* in_sizes, int n_in,
                              void* d_out, int out_size) {
    const float* sa      = (const float*)d_in[0];
    const float* sen     = (const float*)d_in[1];
    const float* W_sar   = (const float*)d_in[2];
    const float* b_sar   = (const float*)d_in[3];
    const float* W_sen   = (const float*)d_in[4];
    const float* b_sen   = (const float*)d_in[5];
    const float* W_resar = (const float*)d_in[6];
    const float* b_resar = (const float*)d_in[7];
    const float* W_resen = (const float*)d_in[8];
    const float* b_resen = (const float*)d_in[9];
    float* out = (float*)d_out;

    q_model_kernel<<<(BQ / 2) / TPB, TPB>>>(sa, sen, W_sar, b_sar, W_sen, b_sen,
                                            W_resar, b_resar, W_resen, b_resen, out);
}

// round 9
// speedup vs baseline: 1.1272x; 1.1272x over previous
#include <cuda_runtime.h>
#include <cuda_bf16.h>

// Q_Model_43782896615432 — analytic collapse of the 6-qubit circuit.
//   Z0=c1*c2, Z1=c0*c1, Z2=c0*c1*c2, Z3=c4*c5, Z4=c3*c4, Z5=c3*c4*c5
// R9: R5's winning shape (TPB=64, 2 samples/thread, 4096 warps, vec I/O)
// with the smem staging replaced by direct vectorized uniform LDGs:
// kills the LDG->STS->BAR->LDS two-hop weight path, the __syncthreads,
// and all smem. Uniform addresses -> broadcast wavefronts, L1-hit.

#define BQ 262144
#define TPB 64

__global__ __launch_bounds__(TPB)
void q_model_kernel(const float* __restrict__ sa,
                    const float* __restrict__ sen,
                    const float* __restrict__ W_sar,  const float* __restrict__ b_sar,
                    const float* __restrict__ W_sen,  const float* __restrict__ b_sen,
                    const float* __restrict__ W_resar, const float* __restrict__ b_resar,
                    const float* __restrict__ W_resen, const float* __restrict__ b_resen,
                    float* __restrict__ out)
{
    const int t = threadIdx.x;
    const int g = blockIdx.x * TPB + t;          // 0 .. 131071, exact (2 samples each)

    // ---- issue ALL loads up front: 6 input LDG.64 + 13 uniform weight LDGs ----
    const float2* sen2 = reinterpret_cast<const float2*>(sen) + 3 * g;
    const float2* sa2  = reinterpret_cast<const float2*>(sa)  + 3 * g;
    const float2 E0 = sen2[0];
    const float2 E1 = sen2[1];
    const float2 E2 = sen2[2];
    const float2 A0 = sa2[0];
    const float2 A1 = sa2[1];
    const float2 A2 = sa2[2];

    // W_sen (9 floats): 2x LDG.128 + LDG.32 ; b_sen (3): LDG.64 + LDG.32
    const float4 ws0 = __ldg(reinterpret_cast<const float4*>(W_sen));      // w0..w3
    const float4 ws1 = __ldg(reinterpret_cast<const float4*>(W_sen) + 1);  // w4..w7
    const float  ws8 = __ldg(W_sen + 8);
    const float2 bs01 = __ldg(reinterpret_cast<const float2*>(b_sen));
    const float  bs2  = __ldg(b_sen + 2);

    // W_sar (9) / b_sar (3)
    const float4 wa0 = __ldg(reinterpret_cast<const float4*>(W_sar));
    const float4 wa1 = __ldg(reinterpret_cast<const float4*>(W_sar) + 1);
    const float  wa8 = __ldg(W_sar + 8);
    const float2 ba01 = __ldg(reinterpret_cast<const float2*>(b_sar));
    const float  ba2  = __ldg(b_sar + 2);

    // W_resar (6): LDG.128 + LDG.64 ; b_resar (2): LDG.64
    const float4 qr0 = __ldg(reinterpret_cast<const float4*>(W_resar));    // q00 q01 q02 q10
    const float2 qr1 = __ldg(reinterpret_cast<const float2*>(W_resar) + 2);// q11 q12
    const float2 qb  = __ldg(reinterpret_cast<const float2*>(b_resar));

    // W_resen (9) / b_resen (3)
    const float4 ur0 = __ldg(reinterpret_cast<const float4*>(W_resen));
    const float4 ur1 = __ldg(reinterpret_cast<const float4*>(W_resen) + 1);
    const float  ur8 = __ldg(W_resen + 8);
    const float2 ub01 = __ldg(reinterpret_cast<const float2*>(b_resen));
    const float  ub2  = __ldg(b_resen + 2);

    const float ein[6] = {E0.x, E0.y, E1.x, E1.y, E2.x, E2.y};
    const float ain[6] = {A0.x, A0.y, A1.x, A1.y, A2.x, A2.y};

    float sarv[4];
    float senv[6];

#pragma unroll
    for (int s = 0; s < 2; s++) {
        const float e0 = ein[3 * s + 0], e1 = ein[3 * s + 1], e2 = ein[3 * s + 2];
        const float a0 = ain[3 * s + 0], a1 = ain[3 * s + 1], a2 = ain[3 * s + 2];

        // theta = W x + b   (rows laid out over the packed vec loads)
        const float t0 = fmaf(ws0.x, e0, fmaf(ws0.y, e1, fmaf(ws0.z, e2, bs01.x)));
        const float t1 = fmaf(ws0.w, e0, fmaf(ws1.x, e1, fmaf(ws1.y, e2, bs01.y)));
        const float t2 = fmaf(ws1.z, e0, fmaf(ws1.w, e1, fmaf(ws8,  e2, bs2)));
        const float t3 = fmaf(wa0.x, a0, fmaf(wa0.y, a1, fmaf(wa0.z, a2, ba01.x)));
        const float t4 = fmaf(wa0.w, a0, fmaf(wa1.x, a1, fmaf(wa1.y, a2, ba01.y)));
        const float t5 = fmaf(wa1.z, a0, fmaf(wa1.w, a1, fmaf(wa8,  a2, ba2)));

        const float c0 = __cosf(t0), c1 = __cosf(t1), c2 = __cosf(t2);
        const float c3 = __cosf(t3), c4 = __cosf(t4), c5 = __cosf(t5);

        const float Z0 = c1 * c2;
        const float Z1 = c0 * c1;
        const float Z2 = Z1 * c2;
        const float Z3 = c4 * c5;
        const float Z4 = c3 * c4;
        const float Z5 = Z4 * c5;

        sarv[2 * s + 0] = fmaf(qr0.x, Z3, fmaf(qr0.y, Z4, fmaf(qr0.z, Z5, qb.x)));
        sarv[2 * s + 1] = fmaf(qr0.w, Z3, fmaf(qr1.x, Z4, fmaf(qr1.y, Z5, qb.y)));

        senv[3 * s + 0] = fmaf(ur0.x, Z0, fmaf(ur0.y, Z1, fmaf(ur0.z, Z2, ub01.x)));
        senv[3 * s + 1] = fmaf(ur0.w, Z0, fmaf(ur1.x, Z1, fmaf(ur1.y, Z2, ub01.y)));
        senv[3 * s + 2] = fmaf(ur1.z, Z0, fmaf(ur1.w, Z1, fmaf(ur8,  Z2, ub2)));
    }

    // ---- outputs: sar [0, 2B) as STG.128; sen [2B, 5B) as 3x STG.64 ----
    reinterpret_cast<float4*>(out)[g] = make_float4(sarv[0], sarv[1], sarv[2], sarv[3]);

    float2* so = reinterpret_cast<float2*>(out + 2 * BQ) + 3 * g;
    so[0] = make_float2(senv[0], senv[1]);
    so[1] = make_float2(senv[2], senv[3]);
    so[2] = make_float2(senv[4], senv[5]);
}

extern "C" void kernel_launch(void* const* d_in, const int* in_sizes, int n_in,
                              void* d_out, int out_size) {
    const float* sa      = (const float*)d_in[0];
    const float* sen     = (const float*)d_in[1];
    const float* W_sar   = (const float*)d_in[2];
    const float* b_sar   = (const float*)d_in[3];
    const float* W_sen   = (const float*)d_in[4];
    const float* b_sen   = (const float*)d_in[5];
    const float* W_resar = (const float*)d_in[6];
    const float* b_resar = (const float*)d_in[7];
    const float* W_resen = (const float*)d_in[8];
    const float* b_resen = (const float*)d_in[9];
    float* out = (float*)d_out;

    q_model_kernel<<<(BQ / 2) / TPB, TPB>>>(sa, sen, W_sar, b_sar, W_sen, b_sen,
                                            W_resar, b_resar, W_resen, b_resen, out);
}

// round 10
// speedup vs baseline: 1.2066x; 1.0704x over previous
#include <cuda_runtime.h>
#include <cuda_bf16.h>

// Q_Model_43782896615432 — analytic collapse of the 6-qubit circuit.
//   Z0=c1*c2, Z1=c0*c1, Z2=c0*c1*c2, Z3=c4*c5, Z4=c3*c4, Z5=c3*c4*c5
// R10: R5 (best: TPB=64, 2 samples/thread, smem weights, vec I/O) with the
// prologue ordering fixed: weight LDG->STS issues BEFORE the input LDGs, so
// the block-wide BAR.SYNC release is gated only by the weight fetch, not by
// six input loads queued ahead of it in the staging threads' LSU FIFO.

#define BQ 262144
#define TPB 64

__global__ __launch_bounds__(TPB)
void q_model_kernel(const float* __restrict__ sa,
                    const float* __restrict__ sen,
                    const float* __restrict__ W_sar,  const float* __restrict__ b_sar,
                    const float* __restrict__ W_sen,  const float* __restrict__ b_sen,
                    const float* __restrict__ W_resar, const float* __restrict__ b_resar,
                    const float* __restrict__ W_resen, const float* __restrict__ b_resen,
                    float* __restrict__ out)
{
    const int t = threadIdx.x;
    const int g = blockIdx.x * TPB + t;          // 0 .. 131071, exact (2 samples each)

    // ---- (1) weight staging FIRST: these gate the barrier for the whole block ----
    // rows 0-2: W_sen/b_sen | 3-5: W_sar/b_sar | 6-7: W_resar/b_resar | 8-10: W_resen/b_resen
    __shared__ float4 P[11];
    if (t < 44) {
        const int row = t >> 2;
        const int c   = t & 3;
        float v;
        if (row < 3)      v = (c < 3) ? W_sen[row * 3 + c]         : b_sen[row];
        else if (row < 6) v = (c < 3) ? W_sar[(row - 3) * 3 + c]   : b_sar[row - 3];
        else if (row < 8) v = (c < 3) ? W_resar[(row - 6) * 3 + c] : b_resar[row - 6];
        else              v = (c < 3) ? W_resen[(row - 8) * 3 + c] : b_resen[row - 8];
        reinterpret_cast<float*>(P)[t] = v;
    }

    // ---- (2) input loads: independent of the barrier, land in parallel ----
    const float2* sen2 = reinterpret_cast<const float2*>(sen) + 3 * g;
    const float2* sa2  = reinterpret_cast<const float2*>(sa)  + 3 * g;
    const float2 E0 = sen2[0];
    const float2 E1 = sen2[1];
    const float2 E2 = sen2[2];
    const float2 A0 = sa2[0];
    const float2 A1 = sa2[1];
    const float2 A2 = sa2[2];

    // ---- (3) barrier: gated only by the weight LDG->STS chain ----
    __syncthreads();

    // ---- param rows (broadcast LDS.128, register-resident) ----
    const float4 r0 = P[0], r1 = P[1], r2 = P[2];   // theta 0-2 (sen branch)
    const float4 r3 = P[3], r4 = P[4], r5 = P[5];   // theta 3-5 (sa branch)
    const float4 q0 = P[6], q1 = P[7];              // sar output rows
    const float4 u0 = P[8], u1 = P[9], u2 = P[10];  // sen output rows

    const float ein[6] = {E0.x, E0.y, E1.x, E1.y, E2.x, E2.y};
    const float ain[6] = {A0.x, A0.y, A1.x, A1.y, A2.x, A2.y};

    float sarv[4];
    float senv[6];

#pragma unroll
    for (int s = 0; s < 2; s++) {
        const float e0 = ein[3 * s + 0], e1 = ein[3 * s + 1], e2 = ein[3 * s + 2];
        const float a0 = ain[3 * s + 0], a1 = ain[3 * s + 1], a2 = ain[3 * s + 2];

        const float t0 = fmaf(r0.x, e0, fmaf(r0.y, e1, fmaf(r0.z, e2, r0.w)));
        const float t1 = fmaf(r1.x, e0, fmaf(r1.y, e1, fmaf(r1.z, e2, r1.w)));
        const float t2 = fmaf(r2.x, e0, fmaf(r2.y, e1, fmaf(r2.z, e2, r2.w)));
        const float t3 = fmaf(r3.x, a0, fmaf(r3.y, a1, fmaf(r3.z, a2, r3.w)));
        const float t4 = fmaf(r4.x, a0, fmaf(r4.y, a1, fmaf(r4.z, a2, r4.w)));
        const float t5 = fmaf(r5.x, a0, fmaf(r5.y, a1, fmaf(r5.z, a2, r5.w)));

        const float c0 = __cosf(t0), c1 = __cosf(t1), c2 = __cosf(t2);
        const float c3 = __cosf(t3), c4 = __cosf(t4), c5 = __cosf(t5);

        const float Z0 = c1 * c2;
        const float Z1 = c0 * c1;
        const float Z2 = Z1 * c2;
        const float Z3 = c4 * c5;
        const float Z4 = c3 * c4;
        const float Z5 = Z4 * c5;

        sarv[2 * s + 0] = fmaf(q0.x, Z3, fmaf(q0.y, Z4, fmaf(q0.z, Z5, q0.w)));
        sarv[2 * s + 1] = fmaf(q1.x, Z3, fmaf(q1.y, Z4, fmaf(q1.z, Z5, q1.w)));

        senv[3 * s + 0] = fmaf(u0.x, Z0, fmaf(u0.y, Z1, fmaf(u0.z, Z2, u0.w)));
        senv[3 * s + 1] = fmaf(u1.x, Z0, fmaf(u1.y, Z1, fmaf(u1.z, Z2, u1.w)));
        senv[3 * s + 2] = fmaf(u2.x, Z0, fmaf(u2.y, Z1, fmaf(u2.z, Z2, u2.w)));
    }

    // ---- outputs: sar [0, 2B) as STG.128; sen [2B, 5B) as 3x STG.64 ----
    reinterpret_cast<float4*>(out)[g] = make_float4(sarv[0], sarv[1], sarv[2], sarv[3]);

    float2* so = reinterpret_cast<float2*>(out + 2 * BQ) + 3 * g;
    so[0] = make_float2(senv[0], senv[1]);
    so[1] = make_float2(senv[2], senv[3]);
    so[2] = make_float2(senv[4], senv[5]);
}

extern "C" void kernel_launch(void* const* d_in, const int* in_sizes, int n_in,
                              void* d_out, int out_size) {
    const float* sa      = (const float*)d_in[0];
    const float* sen     = (const float*)d_in[1];
    const float* W_sar   = (const float*)d_in[2];
    const float* b_sar   = (const float*)d_in[3];
    const float* W_sen   = (const float*)d_in[4];
    const float* b_sen   = (const float*)d_in[5];
    const float* W_resar = (const float*)d_in[6];
    const float* b_resar = (const float*)d_in[7];
    const float* W_resen = (const float*)d_in[8];
    const float* b_resen = (const float*)d_in[9];
    float* out = (float*)d_out;

    q_model_kernel<<<(BQ / 2) / TPB, TPB>>>(sa, sen, W_sar, b_sar, W_sen, b_sen,
                                            W_resar, b_resar, W_resen, b_resen, out);
}